// round 1
// baseline (speedup 1.0000x reference)
#include <cuda_runtime.h>
#include <cuda_bf16.h>
#include <cstdint>
#include <cstddef>

// Problem constants
#define BB   64      // batch
#define LL   49      // encoder locations
#define TT   20      // time steps
#define VV   10000   // vocab
#define EE   512     // embed dim
#define ENCD 2048    // encoder dim
#define DD   512     // decoder dim
#define AA   512     // attention dim
#define KCAT 3072    // E + ENC + D (concat gemm K)

// ---------------- device scratch (static, no allocations) ----------------
__device__ float g_mean[BB * ENCD];
__device__ float g_encproj[BB * LL * AA];          // 6.4 MB
__device__ float g_Wcat[2048 * KCAT];              // 25.2 MB  [j][k]: k<2560 -> W_ih, else W_hh
__device__ float g_bcat[2048];
__device__ float g_h[BB * DD];
__device__ float g_c[BB * DD];
__device__ float g_X[BB * KCAT];                   // [emb | context | h]
__device__ float g_ph[8 * BB * DD];
__device__ float g_pc[8 * BB * DD];
__device__ float g_decp[8 * BB * AA];
__device__ float g_gpart[12 * BB * 2048];          // gates split-K partials
__device__ float g_lpart[2 * BB * VV];             // logits split-K partials

// ---------------- generic GEMM: C(MxN) = A(MxK') * B + bias ----------------
// A row-major, lda = row stride (K-contiguous).
// BT=false: B is (K x N), ldb = N stride (N-contiguous rows)  -> "NN"
// BT=true : B is (N x K), ldb = K stride (K-contiguous rows)  -> "NT"
// K parameter = K-chunk size; blockIdx.z selects chunk z (k0 = z*K).
// If gridDim.z > 1: writes partial to C + z*M*N (ldc must equal N, bias ignored).
// Tile: BM=64, BN=128, BK=32, 128 threads, 8x8 microtile.
template<bool BT>
__global__ void gemm_kernel(const float* __restrict__ A, int lda,
                            const float* __restrict__ B, int ldb,
                            const float* __restrict__ bias,
                            float* __restrict__ C, int ldc,
                            int M, int N, int K)
{
    __shared__ float Ast[32][68];    // [kk][m]
    __shared__ float Bst[32][132];   // [kk][n]

    const int tid = threadIdx.x;          // 0..127
    const int m0  = blockIdx.y * 64;
    const int n0  = blockIdx.x * 128;
    const int z   = blockIdx.z;
    const int k0base = z * K;

    if (gridDim.z > 1) C += (size_t)z * (size_t)M * (size_t)N;

    const int tx = tid & 15;              // 0..15
    const int ty = tid >> 4;              // 0..7

    float acc[8][8];
    #pragma unroll
    for (int i = 0; i < 8; i++)
        #pragma unroll
        for (int j = 0; j < 8; j++) acc[i][j] = 0.f;

    for (int kt = 0; kt < K; kt += 32) {
        const int k0 = k0base + kt;

        // ---- load A tile (64 x 32), transpose into Ast[kk][m]
        {
            const int kp = tid & 7;       // float4 index along k
            const int mr = tid >> 3;      // 0..15
            #pragma unroll
            for (int p = 0; p < 4; p++) {
                const int m  = mr + p * 16;
                const int gm = m0 + m;
                float4 v = make_float4(0.f, 0.f, 0.f, 0.f);
                if (gm < M)
                    v = *(const float4*)(A + (size_t)gm * lda + k0 + kp * 4);
                Ast[kp * 4 + 0][m] = v.x;
                Ast[kp * 4 + 1][m] = v.y;
                Ast[kp * 4 + 2][m] = v.z;
                Ast[kp * 4 + 3][m] = v.w;
            }
        }

        // ---- load B tile (32 x 128) into Bst[kk][n]
        if (BT) {
            const int kp = tid & 7;
            const int nr = tid >> 3;      // 0..15
            #pragma unroll
            for (int p = 0; p < 8; p++) {
                const int n  = nr + p * 16;
                const int gn = n0 + n;
                float4 v = make_float4(0.f, 0.f, 0.f, 0.f);
                if (gn < N)
                    v = *(const float4*)(B + (size_t)gn * ldb + k0 + kp * 4);
                Bst[kp * 4 + 0][n] = v.x;
                Bst[kp * 4 + 1][n] = v.y;
                Bst[kp * 4 + 2][n] = v.z;
                Bst[kp * 4 + 3][n] = v.w;
            }
        } else {
            const int n4 = tid & 31;      // float4 index along n
            const int kr = tid >> 5;      // 0..3
            #pragma unroll
            for (int p = 0; p < 8; p++) {
                const int kk = kr + p * 4;
                const int gn = n0 + n4 * 4;
                const float* bp = B + (size_t)(k0 + kk) * ldb + gn;
                float4 v = make_float4(0.f, 0.f, 0.f, 0.f);
                if (gn + 3 < N) {
                    v = *(const float4*)bp;
                } else {
                    if (gn + 0 < N) v.x = bp[0];
                    if (gn + 1 < N) v.y = bp[1];
                    if (gn + 2 < N) v.z = bp[2];
                    if (gn + 3 < N) v.w = bp[3];
                }
                *(float4*)&Bst[kk][n4 * 4] = v;
            }
        }
        __syncthreads();

        // ---- compute
        #pragma unroll
        for (int kk = 0; kk < 32; kk++) {
            float4 a0 = *(const float4*)&Ast[kk][ty * 4];
            float4 a1 = *(const float4*)&Ast[kk][32 + ty * 4];
            float4 b0 = *(const float4*)&Bst[kk][tx * 4];
            float4 b1 = *(const float4*)&Bst[kk][64 + tx * 4];
            float ar[8] = {a0.x, a0.y, a0.z, a0.w, a1.x, a1.y, a1.z, a1.w};
            float br[8] = {b0.x, b0.y, b0.z, b0.w, b1.x, b1.y, b1.z, b1.w};
            #pragma unroll
            for (int i = 0; i < 8; i++)
                #pragma unroll
                for (int j = 0; j < 8; j++)
                    acc[i][j] = fmaf(ar[i], br[j], acc[i][j]);
        }
        __syncthreads();
    }

    // ---- epilogue
    #pragma unroll
    for (int rh = 0; rh < 2; rh++) {
        #pragma unroll
        for (int i = 0; i < 4; i++) {
            const int r = m0 + rh * 32 + ty * 4 + i;
            if (r >= M) continue;
            #pragma unroll
            for (int ch = 0; ch < 2; ch++) {
                #pragma unroll
                for (int j = 0; j < 4; j++) {
                    const int c = n0 + ch * 64 + tx * 4 + j;
                    if (c >= N) continue;
                    float v = acc[rh * 4 + i][ch * 4 + j];
                    if (bias) v += bias[c];
                    C[(size_t)r * ldc + c] = v;
                }
            }
        }
    }
}

// ---------------- small kernels ----------------
__global__ void prep_kernel(const float* __restrict__ W_ih, const float* __restrict__ W_hh,
                            const float* __restrict__ b_ih, const float* __restrict__ b_hh)
{
    const long total = 2048L * KCAT;
    for (long idx = (long)blockIdx.x * blockDim.x + threadIdx.x; idx < total;
         idx += (long)gridDim.x * blockDim.x) {
        int j = (int)(idx / KCAT);
        int k = (int)(idx % KCAT);
        g_Wcat[idx] = (k < 2560) ? W_ih[(size_t)j * 2560 + k]
                                 : W_hh[(size_t)j * 512 + (k - 2560)];
    }
    int idx = blockIdx.x * blockDim.x + threadIdx.x;
    if (idx < 2048) g_bcat[idx] = b_ih[idx] + b_hh[idx];
}

__global__ void mean_kernel(const float* __restrict__ enc_out)
{
    const int b = blockIdx.x, tid = threadIdx.x;
    for (int e = tid; e < ENCD; e += 256) {
        const float* p = enc_out + (size_t)b * LL * ENCD + e;
        float s = 0.f;
        #pragma unroll 7
        for (int l = 0; l < LL; l++) s += p[(size_t)l * ENCD];
        g_mean[b * ENCD + e] = s * (1.f / (float)LL);
    }
}

__global__ void init_reduce(const float* __restrict__ b_init_h,
                            const float* __restrict__ b_init_c)
{
    int idx = blockIdx.x * blockDim.x + threadIdx.x;  // 64*512
    int d = idx & 511;
    float h = b_init_h[d], c = b_init_c[d];
    #pragma unroll
    for (int z = 0; z < 8; z++) {
        h += g_ph[z * (BB * DD) + idx];
        c += g_pc[z * (BB * DD) + idx];
    }
    g_h[idx] = h;
    g_c[idx] = c;
}

__device__ __forceinline__ float sigmoidf(float x) { return 1.f / (1.f + expf(-x)); }

__global__ void lstm_finalize()
{
    int idx = blockIdx.x * blockDim.x + threadIdx.x;  // 64*512
    int b = idx >> 9, d = idx & 511;
    float gi = g_bcat[d], gf = g_bcat[512 + d], gg = g_bcat[1024 + d], go = g_bcat[1536 + d];
    #pragma unroll
    for (int z = 0; z < 12; z++) {
        const float* p = g_gpart + ((size_t)z * BB + b) * 2048;
        gi += p[d]; gf += p[512 + d]; gg += p[1024 + d]; go += p[1536 + d];
    }
    float i = sigmoidf(gi), f = sigmoidf(gf), o = sigmoidf(go), g = tanhf(gg);
    float c = f * g_c[idx] + i * g;
    float h = o * tanhf(c);
    g_c[idx] = c;
    g_h[idx] = h;
}

__global__ void att_kernel(const float* __restrict__ enc_out,
                           const float* __restrict__ b_dec_att,
                           const float* __restrict__ w_full,
                           const float* __restrict__ b_full,
                           const int*   __restrict__ captions,
                           const float* __restrict__ emb_table,
                           float* __restrict__ alphas_out, int t)
{
    __shared__ float sh_dec[AA];
    __shared__ float sh_w[AA];
    __shared__ float sh_h[DD];
    __shared__ float sh_sc[64];

    const int b = blockIdx.x, tid = threadIdx.x;  // 256 threads
    for (int a = tid; a < AA; a += 256) {
        float s = b_dec_att[a];
        #pragma unroll
        for (int z = 0; z < 8; z++) s += g_decp[((size_t)z * BB + b) * AA + a];
        sh_dec[a] = s;
        sh_w[a]   = w_full[a];
        sh_h[a]   = g_h[b * DD + a];
    }
    __syncthreads();

    const int warp = tid >> 5, lane = tid & 31;
    for (int l = warp; l < LL; l += 8) {
        const float* ep = g_encproj + ((size_t)b * LL + l) * AA;
        float s = 0.f;
        for (int a = lane; a < AA; a += 32) {
            float v = ep[a] + sh_dec[a];
            v = fmaxf(v, 0.f);
            s = fmaf(v, sh_w[a], s);
        }
        #pragma unroll
        for (int o = 16; o; o >>= 1) s += __shfl_xor_sync(0xffffffffu, s, o);
        if (lane == 0) sh_sc[l] = s + b_full[0];
    }
    __syncthreads();

    if (warp == 0) {
        float v0 = (lane < LL) ? sh_sc[lane] : -1e30f;
        float v1 = (lane + 32 < LL) ? sh_sc[lane + 32] : -1e30f;
        float mx = fmaxf(v0, v1);
        #pragma unroll
        for (int o = 16; o; o >>= 1) mx = fmaxf(mx, __shfl_xor_sync(0xffffffffu, mx, o));
        float e0 = (lane < LL) ? expf(v0 - mx) : 0.f;
        float e1 = (lane + 32 < LL) ? expf(v1 - mx) : 0.f;
        float ssum = e0 + e1;
        #pragma unroll
        for (int o = 16; o; o >>= 1) ssum += __shfl_xor_sync(0xffffffffu, ssum, o);
        float inv = 1.f / ssum;
        if (lane < LL) sh_sc[lane] = e0 * inv;
        if (lane + 32 < LL) sh_sc[lane + 32] = e1 * inv;
    }
    __syncthreads();

    // write alphas
    for (int l = tid; l < LL; l += 256)
        alphas_out[((size_t)b * TT + t) * LL + l] = sh_sc[l];

    // build X = [emb | context | h]
    const int cap = captions[b * TT + t];
    const float* er = emb_table + (size_t)cap * EE;
    float* Xb = g_X + (size_t)b * KCAT;
    for (int jx = tid; jx < 512; jx += 256) {
        Xb[jx] = er[jx];
        Xb[2560 + jx] = sh_h[jx];
    }
    for (int e = tid; e < ENCD; e += 256) {
        const float* eb = enc_out + (size_t)b * LL * ENCD + e;
        float s = 0.f;
        #pragma unroll 7
        for (int l = 0; l < LL; l++) s = fmaf(sh_sc[l], eb[(size_t)l * ENCD], s);
        Xb[512 + e] = s;
    }
}

__global__ void logits_reduce(const float* __restrict__ b_out, float* __restrict__ out, int t)
{
    int idx = blockIdx.x * blockDim.x + threadIdx.x;  // 64*10000
    int b = idx / VV, v = idx % VV;
    out[(size_t)b * (TT * VV) + (size_t)t * VV + v] =
        g_lpart[idx] + g_lpart[BB * VV + idx] + b_out[v];
}

// ---------------- host launch ----------------
extern "C" void kernel_launch(void* const* d_in, const int* in_sizes, int n_in,
                              void* d_out, int out_size)
{
    const float* enc_out    = (const float*)d_in[0];
    const int*   captions   = (const int*)  d_in[1];
    const float* emb_table  = (const float*)d_in[2];
    const float* W_enc_att  = (const float*)d_in[3];
    const float* b_enc_att  = (const float*)d_in[4];
    const float* W_dec_att  = (const float*)d_in[5];
    const float* b_dec_att  = (const float*)d_in[6];
    const float* w_full     = (const float*)d_in[7];
    const float* b_full     = (const float*)d_in[8];
    const float* W_ih       = (const float*)d_in[9];
    const float* b_ih       = (const float*)d_in[10];
    const float* W_hh       = (const float*)d_in[11];
    const float* b_hh       = (const float*)d_in[12];
    const float* W_init_h   = (const float*)d_in[13];
    const float* b_init_h   = (const float*)d_in[14];
    const float* W_init_c   = (const float*)d_in[15];
    const float* b_init_c   = (const float*)d_in[16];
    const float* W_out      = (const float*)d_in[17];
    const float* b_out      = (const float*)d_in[18];
    float* out = (float*)d_out;
    float* alphas = out + (size_t)BB * TT * VV;

    float *p_mean, *p_encproj, *p_Wcat, *p_h, *p_X, *p_ph, *p_pc, *p_decp, *p_gpart, *p_lpart;
    cudaGetSymbolAddress((void**)&p_mean,    g_mean);
    cudaGetSymbolAddress((void**)&p_encproj, g_encproj);
    cudaGetSymbolAddress((void**)&p_Wcat,    g_Wcat);
    cudaGetSymbolAddress((void**)&p_h,       g_h);
    cudaGetSymbolAddress((void**)&p_X,       g_X);
    cudaGetSymbolAddress((void**)&p_ph,      g_ph);
    cudaGetSymbolAddress((void**)&p_pc,      g_pc);
    cudaGetSymbolAddress((void**)&p_decp,    g_decp);
    cudaGetSymbolAddress((void**)&p_gpart,   g_gpart);
    cudaGetSymbolAddress((void**)&p_lpart,   g_lpart);

    // one-time setup
    prep_kernel<<<4096, 256>>>(W_ih, W_hh, b_ih, b_hh);
    mean_kernel<<<BB, 256>>>(enc_out);
    // h0/c0: (64x512) = mean(64x2048) @ W_init (2048x512), split-K 8 (Kc=256)
    gemm_kernel<false><<<dim3(4, 1, 8), 128>>>(p_mean, ENCD, W_init_h, DD, nullptr,
                                               p_ph, DD, BB, DD, 256);
    gemm_kernel<false><<<dim3(4, 1, 8), 128>>>(p_mean, ENCD, W_init_c, DD, nullptr,
                                               p_pc, DD, BB, DD, 256);
    init_reduce<<<128, 256>>>(b_init_h, b_init_c);
    // enc_proj: (3136x512) = encoder_out(3136x2048) @ W_enc_att(2048x512)
    gemm_kernel<false><<<dim3(4, 49, 1), 128>>>(enc_out, ENCD, W_enc_att, AA, b_enc_att,
                                                p_encproj, AA, BB * LL, AA, ENCD);

    for (int t = 0; t < TT; t++) {
        // dec_proj partials: (64x512) = h(64x512) @ W_dec_att(512x512), split-K 8 (Kc=64)
        gemm_kernel<false><<<dim3(4, 1, 8), 128>>>(p_h, DD, W_dec_att, AA, nullptr,
                                                   p_decp, AA, BB, AA, 64);
        // attention + softmax + context + X build (+ dec_proj reduce)
        att_kernel<<<BB, 256>>>(enc_out, b_dec_att, w_full, b_full, captions, emb_table,
                                alphas, t);
        // gates partials: (64x2048) = X(64x3072) @ Wcat^T, split-K 12 (Kc=256), NT
        gemm_kernel<true><<<dim3(16, 1, 12), 128>>>(p_X, KCAT, p_Wcat, KCAT, nullptr,
                                                    p_gpart, 2048, BB, 2048, 256);
        // gates reduce + LSTM cell update -> g_h, g_c
        lstm_finalize<<<128, 256>>>();
        // logits partials: (64x10000) = h_new(64x512) @ W_out(512x10000), split-K 2 (Kc=256)
        gemm_kernel<false><<<dim3(79, 1, 2), 128>>>(p_h, DD, W_out, VV, nullptr,
                                                    p_lpart, VV, BB, VV, 256);
        // logits reduce + bias -> d_out
        logits_reduce<<<2500, 256>>>(b_out, out, t);
    }
}

// round 3
// speedup vs baseline: 1.9438x; 1.9438x over previous
#include <cuda_runtime.h>
#include <cuda_bf16.h>
#include <cstdint>
#include <cstddef>

// Problem constants
#define BB   64      // batch
#define LL   49      // encoder locations
#define TT   20      // time steps
#define VV   10000   // vocab
#define EE   512     // embed dim
#define ENCD 2048    // encoder dim
#define DD   512     // decoder dim
#define AA   512     // attention dim
#define NG   2048    // 4*D gate width
#define KC2  2560    // ENC + D  (per-step gates K: [context | h])

#define SMEMB 51200  // dynamic smem for gemm: 2*(32*68 + 32*132)*4 bytes

// ---------------- device scratch (static, no allocations) ----------------
__device__ float g_mean[BB * ENCD];
__device__ float g_eppart[2 * BB * LL * AA];
__device__ float g_encproj[BB * LL * AA];
__device__ float g_Wch[NG * KC2];            // [j][k]: k<2048 -> W_ih[:,512+k], else W_hh
__device__ float g_bcat[NG];
__device__ float g_Eall[TT * BB * EE];       // gathered embeddings, row = t*64+b
__device__ float g_Gemb[TT * BB * NG];       // emb contribution to gates
__device__ float g_h[BB * DD];
__device__ float g_c[BB * DD];
__device__ float g_X2[BB * KC2];             // [context | h]
__device__ float g_hall[TT * BB * DD];       // all h_t, row = t*64+b
__device__ float g_ph[8 * BB * DD];
__device__ float g_pc[8 * BB * DD];
__device__ float g_decp[8 * BB * AA];
__device__ float g_gpart[10 * BB * NG];      // gates split-K partials

// ---------------- packed fp32x2 helpers ----------------
#define FMA2(D,Aq,Bq,Cq) asm("fma.rn.f32x2 %0, %1, %2, %3;" : "=l"(D) : "l"(Aq), "l"(Bq), "l"(Cq))
#define PACK2(D,LO,HI)   asm("mov.b64 %0, {%1, %2};" : "=l"(D) : "f"(LO), "f"(HI))
#define UNPK2(LO,HI,S)   asm("mov.b64 {%0, %1}, %2;" : "=f"(LO), "=f"(HI) : "l"(S))

// ---------------- generic GEMM: C(MxN) = A(MxK') * B (+ bias) ----------------
// A row-major (lda = row stride, K-contiguous).
// BT=false: B is (K x N), ldb = N-row stride.   BT=true: B is (N x K), ldb = K-row stride.
// K arg = K-chunk; blockIdx.z selects chunk (k0 = z*K). If gridDim.z>1 (MODE 0 only):
// writes partial to C + z*M*N, bias must be nullptr.
// MODE 0: C[r*ldc + c].  MODE 1 (logits): row r = t*64+b -> C[(b*TT + t)*VV + c].
// Tile: BM=64, BN=128, BK=32, 256 threads, double-buffered, FFMA2 inner loop.
template<bool BT, int MODE>
__global__ void gemm_kernel(const float* __restrict__ A, int lda,
                            const float* __restrict__ B, int ldb,
                            const float* __restrict__ bias,
                            float* __restrict__ C, int ldc,
                            int M, int N, int K)
{
    extern __shared__ float sm[];
    float* As = sm;                 // [2][32][68]
    float* Bs = sm + 2 * 32 * 68;   // [2][32][132]

    const int tid = threadIdx.x;            // 0..255
    const int m0  = blockIdx.y * 64;
    const int n0  = blockIdx.x * 128;
    const int k0base = blockIdx.z * K;
    if (MODE == 0 && gridDim.z > 1) C += (size_t)blockIdx.z * (size_t)M * (size_t)N;

    const int lane = tid & 31;
    const int warp = tid >> 5;              // ty: rows warp*8..+8
    const int tx = lane;                    // cols tx*4..+4

    // loader indices
    const int a_kp = tid & 7, a_mr = tid >> 3;    // A: 2 x float4 (rows a_mr, a_mr+32)
    const int b_kp = tid & 7, b_nr = tid >> 3;    // B(NT): 4 x float4 (rows b_nr + 32p)
    const int b_n4 = tid & 31, b_kr = tid >> 5;   // B(NN): 4 x float4 (k rows b_kr + 8p)

    float4 Ag[2], Bg[4];
    const float4 z4 = make_float4(0.f, 0.f, 0.f, 0.f);

    unsigned long long acc2[4][4];
    #pragma unroll
    for (int i = 0; i < 4; i++)
        #pragma unroll
        for (int j = 0; j < 4; j++) acc2[i][j] = 0ull;

    // ---- prologue: load tile 0 directly to buffer 0
    {
        const int k0 = k0base;
        #pragma unroll
        for (int p = 0; p < 2; p++) {
            const int gm = m0 + a_mr + p * 32;
            Ag[p] = (gm < M) ? *(const float4*)(A + (size_t)gm * lda + k0 + a_kp * 4) : z4;
        }
        if (BT) {
            #pragma unroll
            for (int p = 0; p < 4; p++) {
                const int gn = n0 + b_nr + p * 32;
                Bg[p] = (gn < N) ? *(const float4*)(B + (size_t)gn * ldb + k0 + b_kp * 4) : z4;
            }
        } else {
            #pragma unroll
            for (int p = 0; p < 4; p++) {
                const int kk = b_kr + p * 8;
                const int gn = n0 + b_n4 * 4;
                const float* bp = B + (size_t)(k0 + kk) * ldb + gn;
                float4 v = z4;
                if (gn + 3 < N) v = *(const float4*)bp;
                else {
                    if (gn + 0 < N) v.x = bp[0];
                    if (gn + 1 < N) v.y = bp[1];
                    if (gn + 2 < N) v.z = bp[2];
                }
                Bg[p] = v;
            }
        }
        // store buf 0
        float* Ad = As;
        #pragma unroll
        for (int p = 0; p < 2; p++) {
            const int m = a_mr + p * 32;
            Ad[(a_kp * 4 + 0) * 68 + m] = Ag[p].x;
            Ad[(a_kp * 4 + 1) * 68 + m] = Ag[p].y;
            Ad[(a_kp * 4 + 2) * 68 + m] = Ag[p].z;
            Ad[(a_kp * 4 + 3) * 68 + m] = Ag[p].w;
        }
        float* Bd = Bs;
        if (BT) {
            #pragma unroll
            for (int p = 0; p < 4; p++) {
                const int n = b_nr + p * 32;
                Bd[(b_kp * 4 + 0) * 132 + n] = Bg[p].x;
                Bd[(b_kp * 4 + 1) * 132 + n] = Bg[p].y;
                Bd[(b_kp * 4 + 2) * 132 + n] = Bg[p].z;
                Bd[(b_kp * 4 + 3) * 132 + n] = Bg[p].w;
            }
        } else {
            #pragma unroll
            for (int p = 0; p < 4; p++) {
                const int kk = b_kr + p * 8;
                *(float4*)&Bd[kk * 132 + b_n4 * 4] = Bg[p];
            }
        }
    }
    __syncthreads();

    int cur = 0;
    for (int kt = 0; kt < K; kt += 32) {
        const bool has_next = (kt + 32 < K);
        if (has_next) {
            const int k0 = k0base + kt + 32;
            #pragma unroll
            for (int p = 0; p < 2; p++) {
                const int gm = m0 + a_mr + p * 32;
                Ag[p] = (gm < M) ? *(const float4*)(A + (size_t)gm * lda + k0 + a_kp * 4) : z4;
            }
            if (BT) {
                #pragma unroll
                for (int p = 0; p < 4; p++) {
                    const int gn = n0 + b_nr + p * 32;
                    Bg[p] = (gn < N) ? *(const float4*)(B + (size_t)gn * ldb + k0 + b_kp * 4) : z4;
                }
            } else {
                #pragma unroll
                for (int p = 0; p < 4; p++) {
                    const int kk = b_kr + p * 8;
                    const int gn = n0 + b_n4 * 4;
                    const float* bp = B + (size_t)(k0 + kk) * ldb + gn;
                    float4 v = z4;
                    if (gn + 3 < N) v = *(const float4*)bp;
                    else {
                        if (gn + 0 < N) v.x = bp[0];
                        if (gn + 1 < N) v.y = bp[1];
                        if (gn + 2 < N) v.z = bp[2];
                    }
                    Bg[p] = v;
                }
            }
        }

        // ---- compute on buffer cur (FFMA2: rows paired)
        const float* Ab = As + cur * 2176;
        const float* Bb = Bs + cur * 4224;
        #pragma unroll
        for (int kk = 0; kk < 32; kk++) {
            const float* Ak = Ab + kk * 68 + warp * 8;
            const float* Bk = Bb + kk * 132 + tx * 4;
            ulonglong2 av0 = *(const ulonglong2*)(Ak);      // rows (0,1),(2,3)
            ulonglong2 av1 = *(const ulonglong2*)(Ak + 4);  // rows (4,5),(6,7)
            float4 bv = *(const float4*)(Bk);
            unsigned long long a2[4] = {av0.x, av0.y, av1.x, av1.y};
            unsigned long long b2[4];
            PACK2(b2[0], bv.x, bv.x);
            PACK2(b2[1], bv.y, bv.y);
            PACK2(b2[2], bv.z, bv.z);
            PACK2(b2[3], bv.w, bv.w);
            #pragma unroll
            for (int i = 0; i < 4; i++)
                #pragma unroll
                for (int j = 0; j < 4; j++)
                    FMA2(acc2[i][j], a2[i], b2[j], acc2[i][j]);
        }

        if (has_next) {
            const int nb = cur ^ 1;
            float* Ad = As + nb * 2176;
            #pragma unroll
            for (int p = 0; p < 2; p++) {
                const int m = a_mr + p * 32;
                Ad[(a_kp * 4 + 0) * 68 + m] = Ag[p].x;
                Ad[(a_kp * 4 + 1) * 68 + m] = Ag[p].y;
                Ad[(a_kp * 4 + 2) * 68 + m] = Ag[p].z;
                Ad[(a_kp * 4 + 3) * 68 + m] = Ag[p].w;
            }
            float* Bd = Bs + nb * 4224;
            if (BT) {
                #pragma unroll
                for (int p = 0; p < 4; p++) {
                    const int n = b_nr + p * 32;
                    Bd[(b_kp * 4 + 0) * 132 + n] = Bg[p].x;
                    Bd[(b_kp * 4 + 1) * 132 + n] = Bg[p].y;
                    Bd[(b_kp * 4 + 2) * 132 + n] = Bg[p].z;
                    Bd[(b_kp * 4 + 3) * 132 + n] = Bg[p].w;
                }
            } else {
                #pragma unroll
                for (int p = 0; p < 4; p++) {
                    const int kk = b_kr + p * 8;
                    *(float4*)&Bd[kk * 132 + b_n4 * 4] = Bg[p];
                }
            }
        }
        __syncthreads();
        cur ^= 1;
    }

    // ---- epilogue
    #pragma unroll
    for (int ip = 0; ip < 4; ip++) {
        const int r0 = m0 + warp * 8 + ip * 2;
        #pragma unroll
        for (int j = 0; j < 4; j++) {
            const int c = n0 + tx * 4 + j;
            if (c >= N) continue;
            float v0, v1;
            UNPK2(v0, v1, acc2[ip][j]);
            const float bv = bias ? bias[c] : 0.f;
            if (MODE == 0) {
                if (r0 < M)     C[(size_t)r0 * ldc + c]       = v0 + bv;
                if (r0 + 1 < M) C[(size_t)(r0 + 1) * ldc + c] = v1 + bv;
            } else {
                const int t0 = r0 >> 6, bq0 = r0 & 63;
                const int t1 = (r0 + 1) >> 6, bq1 = (r0 + 1) & 63;
                C[((size_t)bq0 * TT + t0) * VV + c] = v0 + bv;
                C[((size_t)bq1 * TT + t1) * VV + c] = v1 + bv;
            }
        }
    }
}

// ---------------- small kernels ----------------
__global__ void prep_kernel(const float* __restrict__ W_ih, const float* __restrict__ W_hh,
                            const float* __restrict__ b_ih, const float* __restrict__ b_hh)
{
    const long total = (long)NG * KC2;
    for (long idx = (long)blockIdx.x * blockDim.x + threadIdx.x; idx < total;
         idx += (long)gridDim.x * blockDim.x) {
        int j = (int)(idx / KC2);
        int k = (int)(idx % KC2);
        g_Wch[idx] = (k < ENCD) ? W_ih[(size_t)j * 2560 + 512 + k]
                                : W_hh[(size_t)j * 512 + (k - ENCD)];
    }
    int idx = blockIdx.x * blockDim.x + threadIdx.x;
    if (idx < NG) g_bcat[idx] = b_ih[idx] + b_hh[idx];
}

__global__ void gather_emb(const int* __restrict__ captions,
                           const float* __restrict__ emb_table)
{
    int idx = blockIdx.x * blockDim.x + threadIdx.x;  // TT*BB*EE
    if (idx >= TT * BB * EE) return;
    int e  = idx & 511;
    int rb = idx >> 9;          // t*64 + b
    int tq = rb >> 6, bq = rb & 63;
    g_Eall[idx] = emb_table[(size_t)captions[bq * TT + tq] * EE + e];
}

__global__ void mean_kernel(const float* __restrict__ enc_out)
{
    const int b = blockIdx.x, tid = threadIdx.x;
    for (int e = tid; e < ENCD; e += 256) {
        const float* p = enc_out + (size_t)b * LL * ENCD + e;
        float s = 0.f;
        #pragma unroll 7
        for (int l = 0; l < LL; l++) s += p[(size_t)l * ENCD];
        g_mean[b * ENCD + e] = s * (1.f / (float)LL);
    }
}

__global__ void init_reduce(const float* __restrict__ b_init_h,
                            const float* __restrict__ b_init_c)
{
    int idx = blockIdx.x * blockDim.x + threadIdx.x;  // 64*512
    int b = idx >> 9, d = idx & 511;
    float h = b_init_h[d], c = b_init_c[d];
    #pragma unroll
    for (int z = 0; z < 8; z++) {
        h += g_ph[z * (BB * DD) + idx];
        c += g_pc[z * (BB * DD) + idx];
    }
    g_h[idx] = h;
    g_c[idx] = c;
    g_X2[(size_t)b * KC2 + ENCD + d] = h;
}

__global__ void ep_reduce(const float* __restrict__ b_enc_att)
{
    int idx = blockIdx.x * blockDim.x + threadIdx.x;  // BB*LL*AA
    int a = idx & 511;
    g_encproj[idx] = g_eppart[idx] + g_eppart[BB * LL * AA + idx] + b_enc_att[a];
}

__device__ __forceinline__ float sigmoidf(float x) { return 1.f / (1.f + expf(-x)); }

__global__ void lstm_finalize(int t)
{
    int idx = blockIdx.x * blockDim.x + threadIdx.x;  // 64*512
    int b = idx >> 9, d = idx & 511;
    const float* ge = g_Gemb + ((size_t)t * BB + b) * NG;
    float gi = g_bcat[d]        + ge[d];
    float gf = g_bcat[512 + d]  + ge[512 + d];
    float gg = g_bcat[1024 + d] + ge[1024 + d];
    float go = g_bcat[1536 + d] + ge[1536 + d];
    #pragma unroll
    for (int z = 0; z < 10; z++) {
        const float* p = g_gpart + ((size_t)z * BB + b) * NG;
        gi += p[d]; gf += p[512 + d]; gg += p[1024 + d]; go += p[1536 + d];
    }
    float i = sigmoidf(gi), f = sigmoidf(gf), o = sigmoidf(go), g = tanhf(gg);
    float c = f * g_c[idx] + i * g;
    float h = o * tanhf(c);
    g_c[idx] = c;
    g_h[idx] = h;
    g_X2[(size_t)b * KC2 + ENCD + d] = h;
    g_hall[((size_t)t * BB + b) * DD + d] = h;
}

__global__ void att_kernel(const float* __restrict__ enc_out,
                           const float* __restrict__ b_dec_att,
                           const float* __restrict__ w_full,
                           const float* __restrict__ b_full,
                           float* __restrict__ alphas_out, int t)
{
    __shared__ float sh_dec[AA];
    __shared__ float sh_w[AA];
    __shared__ float sh_sc[64];

    const int b = blockIdx.x, tid = threadIdx.x;  // 256 threads
    for (int a = tid; a < AA; a += 256) {
        float s = b_dec_att[a];
        #pragma unroll
        for (int z = 0; z < 8; z++) s += g_decp[((size_t)z * BB + b) * AA + a];
        sh_dec[a] = s;
        sh_w[a]   = w_full[a];
    }
    __syncthreads();

    const int warp = tid >> 5, lane = tid & 31;
    for (int l = warp; l < LL; l += 8) {
        const float* ep = g_encproj + ((size_t)b * LL + l) * AA;
        float s = 0.f;
        for (int a = lane; a < AA; a += 32) {
            float v = ep[a] + sh_dec[a];
            v = fmaxf(v, 0.f);
            s = fmaf(v, sh_w[a], s);
        }
        #pragma unroll
        for (int o = 16; o; o >>= 1) s += __shfl_xor_sync(0xffffffffu, s, o);
        if (lane == 0) sh_sc[l] = s + b_full[0];
    }
    __syncthreads();

    if (warp == 0) {
        float v0 = (lane < LL) ? sh_sc[lane] : -1e30f;
        float v1 = (lane + 32 < LL) ? sh_sc[lane + 32] : -1e30f;
        float mx = fmaxf(v0, v1);
        #pragma unroll
        for (int o = 16; o; o >>= 1) mx = fmaxf(mx, __shfl_xor_sync(0xffffffffu, mx, o));
        float e0 = (lane < LL) ? expf(v0 - mx) : 0.f;
        float e1 = (lane + 32 < LL) ? expf(v1 - mx) : 0.f;
        float ssum = e0 + e1;
        #pragma unroll
        for (int o = 16; o; o >>= 1) ssum += __shfl_xor_sync(0xffffffffu, ssum, o);
        float inv = 1.f / ssum;
        if (lane < LL) sh_sc[lane] = e0 * inv;
        if (lane + 32 < LL) sh_sc[lane + 32] = e1 * inv;
    }
    __syncthreads();

    for (int l = tid; l < LL; l += 256)
        alphas_out[((size_t)b * TT + t) * LL + l] = sh_sc[l];

    // context -> g_X2[:, 0:2048]
    for (int e = tid; e < ENCD; e += 256) {
        const float* eb = enc_out + (size_t)b * LL * ENCD + e;
        float s = 0.f;
        #pragma unroll 7
        for (int l = 0; l < LL; l++) s = fmaf(sh_sc[l], eb[(size_t)l * ENCD], s);
        g_X2[(size_t)b * KC2 + e] = s;
    }
}

// ---------------- host launch ----------------
extern "C" void kernel_launch(void* const* d_in, const int* in_sizes, int n_in,
                              void* d_out, int out_size)
{
    const float* enc_out    = (const float*)d_in[0];
    const int*   captions   = (const int*)  d_in[1];
    const float* emb_table  = (const float*)d_in[2];
    const float* W_enc_att  = (const float*)d_in[3];
    const float* b_enc_att  = (const float*)d_in[4];
    const float* W_dec_att  = (const float*)d_in[5];
    const float* b_dec_att  = (const float*)d_in[6];
    const float* w_full     = (const float*)d_in[7];
    const float* b_full     = (const float*)d_in[8];
    const float* W_ih       = (const float*)d_in[9];
    const float* b_ih       = (const float*)d_in[10];
    const float* W_hh       = (const float*)d_in[11];
    const float* b_hh       = (const float*)d_in[12];
    const float* W_init_h   = (const float*)d_in[13];
    const float* b_init_h   = (const float*)d_in[14];
    const float* W_init_c   = (const float*)d_in[15];
    const float* b_init_c   = (const float*)d_in[16];
    const float* W_out      = (const float*)d_in[17];
    const float* b_out      = (const float*)d_in[18];
    float* out = (float*)d_out;
    float* alphas = out + (size_t)BB * TT * VV;

    cudaFuncSetAttribute(gemm_kernel<false, 0>, cudaFuncAttributeMaxDynamicSharedMemorySize, SMEMB);
    cudaFuncSetAttribute(gemm_kernel<true, 0>,  cudaFuncAttributeMaxDynamicSharedMemorySize, SMEMB);
    cudaFuncSetAttribute(gemm_kernel<false, 1>, cudaFuncAttributeMaxDynamicSharedMemorySize, SMEMB);

    float *p_mean, *p_eppart, *p_Wch, *p_Eall, *p_Gemb, *p_h, *p_X2, *p_hall,
          *p_ph, *p_pc, *p_decp, *p_gpart;
    cudaGetSymbolAddress((void**)&p_mean,   g_mean);
    cudaGetSymbolAddress((void**)&p_eppart, g_eppart);
    cudaGetSymbolAddress((void**)&p_Wch,    g_Wch);
    cudaGetSymbolAddress((void**)&p_Eall,   g_Eall);
    cudaGetSymbolAddress((void**)&p_Gemb,   g_Gemb);
    cudaGetSymbolAddress((void**)&p_h,      g_h);
    cudaGetSymbolAddress((void**)&p_X2,     g_X2);
    cudaGetSymbolAddress((void**)&p_hall,   g_hall);
    cudaGetSymbolAddress((void**)&p_ph,     g_ph);
    cudaGetSymbolAddress((void**)&p_pc,     g_pc);
    cudaGetSymbolAddress((void**)&p_decp,   g_decp);
    cudaGetSymbolAddress((void**)&p_gpart,  g_gpart);

    // ---- one-time setup
    prep_kernel<<<4096, 256>>>(W_ih, W_hh, b_ih, b_hh);
    gather_emb<<<2560, 256>>>(captions, emb_table);
    mean_kernel<<<BB, 256>>>(enc_out);
    // Gemb (1280 x 2048) = Eall(1280x512) @ W_ih[:, :512]^T (NT, ldb=2560)
    gemm_kernel<true, 0><<<dim3(16, 20, 1), 256, SMEMB>>>(p_Eall, EE, W_ih, 2560, nullptr,
                                                          p_Gemb, NG, TT * BB, NG, EE);
    // h0/c0: (64x512) = mean @ W_init, split-K 8 (Kc=256)
    gemm_kernel<false, 0><<<dim3(4, 1, 8), 256, SMEMB>>>(p_mean, ENCD, W_init_h, DD, nullptr,
                                                         p_ph, DD, BB, DD, 256);
    gemm_kernel<false, 0><<<dim3(4, 1, 8), 256, SMEMB>>>(p_mean, ENCD, W_init_c, DD, nullptr,
                                                         p_pc, DD, BB, DD, 256);
    init_reduce<<<128, 256>>>(b_init_h, b_init_c);
    // enc_proj: (3136x512) = encoder_out @ W_enc_att, split-K 2 (Kc=1024)
    gemm_kernel<false, 0><<<dim3(4, 49, 2), 256, SMEMB>>>(enc_out, ENCD, W_enc_att, AA, nullptr,
                                                          p_eppart, AA, BB * LL, AA, 1024);
    ep_reduce<<<6272, 256>>>(b_enc_att);

    // ---- sequential loop (logits removed from critical path)
    for (int t = 0; t < TT; t++) {
        // dec_proj partials: (64x512) = h @ W_dec_att, split-K 8 (Kc=64)
        gemm_kernel<false, 0><<<dim3(4, 1, 8), 256, SMEMB>>>(p_h, DD, W_dec_att, AA, nullptr,
                                                             p_decp, AA, BB, AA, 64);
        // attention + softmax + context -> X2[:, :2048] (+ dec_proj reduce)
        att_kernel<<<BB, 256>>>(enc_out, b_dec_att, w_full, b_full, alphas, t);
        // gates partials: (64x2048) = X2(64x2560) @ Wch^T, split-K 10 (Kc=256)
        gemm_kernel<true, 0><<<dim3(16, 1, 10), 256, SMEMB>>>(p_X2, KC2, p_Wch, KC2, nullptr,
                                                              p_gpart, NG, BB, NG, 256);
        // gates reduce (+Gemb[t] +bias) + LSTM cell -> h, c, X2 h-part, hall[t]
        lstm_finalize<<<128, 256>>>(t);
    }

    // ---- batched logits: (1280 x 10000) = hall @ W_out, custom (b,t) epilogue + bias
    gemm_kernel<false, 1><<<dim3(79, 20, 1), 256, SMEMB>>>(p_hall, DD, W_out, VV, b_out,
                                                           out, VV, TT * BB, VV, 512);
}

// round 7
// speedup vs baseline: 2.8737x; 1.4784x over previous
#include <cuda_runtime.h>
#include <cuda_bf16.h>
#include <cstdint>
#include <cstddef>

// Problem constants
#define BB   64
#define LL   49
#define TT   20
#define VV   10000
#define EE   512
#define ENCD 2048
#define DD   512
#define AA   512
#define NG   2048
#define KC2  2560    // ENC + D

#define SMEMB 51200  // fp32 gemm dynamic smem

// ---------------- device scratch (static, no allocations) ----------------
__device__ float g_mean[BB * ENCD];
__device__ float g_encproj[BB * LL * AA];
__device__ float g_bcat[NG];
__device__ float g_Eall[TT * BB * EE];
__device__ float g_Gemb[TT * BB * NG];
__device__ float g_h[BB * DD];
__device__ float g_c[BB * DD];
__device__ float g_X2[BB * KC2];
__device__ float g_hall[TT * BB * DD];
__device__ float g_ph[8 * BB * DD];
__device__ float g_pc[8 * BB * DD];
__device__ float g_decp[8 * BB * AA];
__device__ float g_gpart[10 * BB * NG];
// pre-split bf16 weights (hi/lo), all K-contiguous rows
__device__ __nv_bfloat16 g_Wch_h[NG * KC2],  g_Wch_l[NG * KC2];    // (2048 x 2560)
__device__ __nv_bfloat16 g_Wout_h[VV * DD],  g_Wout_l[VV * DD];    // (10000 x 512)
__device__ __nv_bfloat16 g_Wenc_h[AA * ENCD], g_Wenc_l[AA * ENCD]; // (512 x 2048)
__device__ __nv_bfloat16 g_Wemb_h[NG * EE],  g_Wemb_l[NG * EE];    // (2048 x 512)

// ---------------- helpers ----------------
__device__ __forceinline__ uint32_t smem_u32(const void* p) {
    uint32_t a;
    asm("{ .reg .u64 t; cvta.to.shared.u64 t, %1; cvt.u32.u64 %0, t; }" : "=r"(a) : "l"(p));
    return a;
}
__device__ __forceinline__ uint32_t sw128(uint32_t off) { return off ^ ((off >> 3) & 0x70); }

__device__ __forceinline__ void split2(float x, float y, uint32_t& hi, uint32_t& lo) {
    __nv_bfloat16 hx = __float2bfloat16_rn(x), hy = __float2bfloat16_rn(y);
    __nv_bfloat16 lx = __float2bfloat16_rn(x - __bfloat162float(hx));
    __nv_bfloat16 ly = __float2bfloat16_rn(y - __bfloat162float(hy));
    __nv_bfloat162 h; h.x = hx; h.y = hy;
    __nv_bfloat162 l; l.x = lx; l.y = ly;
    hi = *(uint32_t*)&h;
    lo = *(uint32_t*)&l;
}

__device__ __forceinline__ void ldsm4(uint32_t a, uint32_t& r0, uint32_t& r1,
                                      uint32_t& r2, uint32_t& r3) {
    asm volatile("ldmatrix.sync.aligned.m8n8.x4.shared.b16 {%0,%1,%2,%3}, [%4];"
                 : "=r"(r0), "=r"(r1), "=r"(r2), "=r"(r3) : "r"(a));
}
__device__ __forceinline__ void mma16816(float* d, const uint32_t* a, const uint32_t* b) {
    asm volatile("mma.sync.aligned.m16n8k16.row.col.f32.bf16.bf16.f32 "
                 "{%0,%1,%2,%3}, {%4,%5,%6,%7}, {%8,%9}, {%0,%1,%2,%3};"
                 : "+f"(d[0]), "+f"(d[1]), "+f"(d[2]), "+f"(d[3])
                 : "r"(a[0]), "r"(a[1]), "r"(a[2]), "r"(a[3]), "r"(b[0]), "r"(b[1]));
}

// ---------------- mma.sync split-bf16 GEMM: C(MxN) = A(MxK) * B(NxK)^T ----------------
// A fp32 row-major (lda). B prepacked bf16 hi/lo, (N x K) K-contiguous (ldb).
// K arg = K-chunk; blockIdx.z selects chunk. gridDim.z>1 -> partial to C + z*M*N (no bias).
// MODE 0: C[r*ldc+c]. MODE 1 (logits): row r=t*64+b -> C[(b*TT+t)*VV+c].
// BN=128, BK=64 bf16 (128B SW128 rows). 256 threads, 8 warps.
template<int BM, int MODE>
__global__ void __launch_bounds__(256)
mma_gemm(const float* __restrict__ A, int lda,
         const __nv_bfloat16* __restrict__ Bhi, const __nv_bfloat16* __restrict__ Blo,
         int ldb, const float* __restrict__ bias,
         float* __restrict__ C, int ldc, int M, int N, int K)
{
    constexpr int ASZ = BM * 128;           // bytes per A precision tile
    constexpr int NJ  = (BM == 128) ? 4 : 2; // n8-pairs per warp
    extern __shared__ __align__(1024) char smem[];
    const uint32_t sb = smem_u32(smem);
    const uint32_t AHI = 0, ALO = ASZ, BHI = 2 * ASZ, BLO = 2 * ASZ + 16384;

    const int tid = threadIdx.x, lane = tid & 31, wid = tid >> 5;
    const int m0 = blockIdx.y * BM, n0 = blockIdx.x * 128;
    const int kbase = blockIdx.z * K;
    if (gridDim.z > 1) C += (size_t)blockIdx.z * (size_t)M * (size_t)N;

    const int wm = (BM == 128) ? (wid & 3) * 32 : (wid & 1) * 32;
    const int wn = (BM == 128) ? (wid >> 2) * 64 : (wid >> 1) * 32;

    const int lr = lane & 7, lm = lane >> 3;  // ldmatrix lane decomposition

    float acc[2][2 * NJ][4];
    #pragma unroll
    for (int i = 0; i < 2; i++)
        #pragma unroll
        for (int j = 0; j < 2 * NJ; j++)
            #pragma unroll
            for (int q = 0; q < 4; q++) acc[i][j][q] = 0.f;

    for (int kc = 0; kc < K; kc += 64) {
        // ---- A: load fp32, split to bf16 hi/lo, swizzled store
        constexpr int AIT = BM / 32;   // 16B chunks per thread
        #pragma unroll
        for (int p = 0; p < AIT; p++) {
            const int i = tid + 256 * p;           // 0 .. BM*8-1
            const int row = i >> 3, c16 = i & 7;
            const int gm = m0 + row;
            float4 v0 = make_float4(0.f, 0.f, 0.f, 0.f), v1 = v0;
            if (gm < M) {
                const float* ap = A + (size_t)gm * lda + kbase + kc + c16 * 8;
                v0 = *(const float4*)ap;
                v1 = *(const float4*)(ap + 4);
            }
            uint4 hv, lv;
            split2(v0.x, v0.y, hv.x, lv.x);
            split2(v0.z, v0.w, hv.y, lv.y);
            split2(v1.x, v1.y, hv.z, lv.z);
            split2(v1.z, v1.w, hv.w, lv.w);
            const uint32_t so = sw128((uint32_t)(row * 128 + c16 * 16));
            *(uint4*)(smem + AHI + so) = hv;
            *(uint4*)(smem + ALO + so) = lv;
        }
        // ---- B: prepacked bf16 hi/lo, swizzled store
        #pragma unroll
        for (int p = 0; p < 4; p++) {
            const int i = tid + 256 * p;           // 0..1023
            const int row = i >> 3, c16 = i & 7;
            const int gn = n0 + row;
            uint4 vh = make_uint4(0, 0, 0, 0), vl = vh;
            if (gn < N) {
                vh = *(const uint4*)(Bhi + (size_t)gn * ldb + kbase + kc + c16 * 8);
                vl = *(const uint4*)(Blo + (size_t)gn * ldb + kbase + kc + c16 * 8);
            }
            const uint32_t so = sw128((uint32_t)(row * 128 + c16 * 16));
            *(uint4*)(smem + BHI + so) = vh;
            *(uint4*)(smem + BLO + so) = vl;
        }
        __syncthreads();

        // ---- 4 k16 steps
        #pragma unroll
        for (int kk = 0; kk < 4; kk++) {
            uint32_t ah[2][4], al[2][4];
            #pragma unroll
            for (int mt = 0; mt < 2; mt++) {
                const uint32_t off = sw128((uint32_t)(
                    (wm + mt * 16 + (lm & 1) * 8 + lr) * 128 + kk * 32 + (lm >> 1) * 16));
                ldsm4(sb + AHI + off, ah[mt][0], ah[mt][1], ah[mt][2], ah[mt][3]);
                ldsm4(sb + ALO + off, al[mt][0], al[mt][1], al[mt][2], al[mt][3]);
            }
            #pragma unroll
            for (int j = 0; j < NJ; j++) {
                const uint32_t offb = sw128((uint32_t)(
                    (wn + j * 16 + (lm >> 1) * 8 + lr) * 128 + kk * 32 + (lm & 1) * 16));
                uint32_t bh[4], bl[4];
                ldsm4(sb + BHI + offb, bh[0], bh[1], bh[2], bh[3]);
                ldsm4(sb + BLO + offb, bl[0], bl[1], bl[2], bl[3]);
                #pragma unroll
                for (int mt = 0; mt < 2; mt++) {
                    #pragma unroll
                    for (int h = 0; h < 2; h++) {
                        float* d = acc[mt][j * 2 + h];
                        mma16816(d, ah[mt], bh + 2 * h);
                        mma16816(d, ah[mt], bl + 2 * h);
                        mma16816(d, al[mt], bh + 2 * h);
                    }
                }
            }
        }
        __syncthreads();
    }

    // ---- epilogue
    const int r_lane = lane >> 2;
    const int c_lane = (lane & 3) * 2;
    #pragma unroll
    for (int mt = 0; mt < 2; mt++) {
        #pragma unroll
        for (int nt = 0; nt < 2 * NJ; nt++) {
            const int c = n0 + wn + nt * 8 + c_lane;
            if (c >= N) continue;
            const float b0 = bias ? bias[c] : 0.f;
            const float b1 = bias ? bias[c + 1] : 0.f;
            #pragma unroll
            for (int hh = 0; hh < 2; hh++) {
                const int r = m0 + wm + mt * 16 + r_lane + hh * 8;
                if (r >= M) continue;
                float2 v;
                v.x = acc[mt][nt][hh * 2 + 0] + b0;
                v.y = acc[mt][nt][hh * 2 + 1] + b1;
                if (MODE == 0) {
                    *(float2*)&C[(size_t)r * ldc + c] = v;
                } else {
                    const int tq = r >> 6, bq = r & 63;
                    *(float2*)&C[((size_t)bq * TT + tq) * VV + c] = v;
                }
            }
        }
    }
}

// ---------------- packed fp32x2 helpers ----------------
#define FMA2(D,Aq,Bq,Cq) asm("fma.rn.f32x2 %0, %1, %2, %3;" : "=l"(D) : "l"(Aq), "l"(Bq), "l"(Cq))
#define PACK2(D,LO,HI)   asm("mov.b64 %0, {%1, %2};" : "=l"(D) : "f"(LO), "f"(HI))
#define UNPK2(LO,HI,S)   asm("mov.b64 {%0, %1}, %2;" : "=f"(LO), "=f"(HI) : "l"(S))

// ---------------- fp32 FFMA2 GEMM (small GEMMs only, NN layout) ----------------
__global__ void gemm_f32(const float* __restrict__ A, int lda,
                         const float* __restrict__ B, int ldb,
                         float* __restrict__ C, int M, int N, int K)
{
    extern __shared__ float sm[];
    float* As = sm;
    float* Bs = sm + 2 * 32 * 68;

    const int tid = threadIdx.x;
    const int m0  = blockIdx.y * 64;
    const int n0  = blockIdx.x * 128;
    const int k0base = blockIdx.z * K;
    if (gridDim.z > 1) C += (size_t)blockIdx.z * (size_t)M * (size_t)N;

    const int lane = tid & 31, warp = tid >> 5, tx = lane;
    const int a_kp = tid & 7, a_mr = tid >> 3;
    const int b_n4 = tid & 31, b_kr = tid >> 5;

    float4 Ag[2], Bg[4];
    const float4 z4 = make_float4(0.f, 0.f, 0.f, 0.f);

    unsigned long long acc2[4][4];
    #pragma unroll
    for (int i = 0; i < 4; i++)
        #pragma unroll
        for (int j = 0; j < 4; j++) acc2[i][j] = 0ull;

    {
        const int k0 = k0base;
        #pragma unroll
        for (int p = 0; p < 2; p++) {
            const int gm = m0 + a_mr + p * 32;
            Ag[p] = (gm < M) ? *(const float4*)(A + (size_t)gm * lda + k0 + a_kp * 4) : z4;
        }
        #pragma unroll
        for (int p = 0; p < 4; p++) {
            const int kk = b_kr + p * 8;
            const int gn = n0 + b_n4 * 4;
            Bg[p] = (gn + 3 < N) ? *(const float4*)(B + (size_t)(k0 + kk) * ldb + gn) : z4;
        }
        float* Ad = As;
        #pragma unroll
        for (int p = 0; p < 2; p++) {
            const int m = a_mr + p * 32;
            Ad[(a_kp * 4 + 0) * 68 + m] = Ag[p].x;
            Ad[(a_kp * 4 + 1) * 68 + m] = Ag[p].y;
            Ad[(a_kp * 4 + 2) * 68 + m] = Ag[p].z;
            Ad[(a_kp * 4 + 3) * 68 + m] = Ag[p].w;
        }
        float* Bd = Bs;
        #pragma unroll
        for (int p = 0; p < 4; p++)
            *(float4*)&Bd[(b_kr + p * 8) * 132 + b_n4 * 4] = Bg[p];
    }
    __syncthreads();

    int cur = 0;
    for (int kt = 0; kt < K; kt += 32) {
        const bool has_next = (kt + 32 < K);
        if (has_next) {
            const int k0 = k0base + kt + 32;
            #pragma unroll
            for (int p = 0; p < 2; p++) {
                const int gm = m0 + a_mr + p * 32;
                Ag[p] = (gm < M) ? *(const float4*)(A + (size_t)gm * lda + k0 + a_kp * 4) : z4;
            }
            #pragma unroll
            for (int p = 0; p < 4; p++) {
                const int kk = b_kr + p * 8;
                const int gn = n0 + b_n4 * 4;
                Bg[p] = (gn + 3 < N) ? *(const float4*)(B + (size_t)(k0 + kk) * ldb + gn) : z4;
            }
        }
        const float* Ab = As + cur * 2176;
        const float* Bb = Bs + cur * 4224;
        #pragma unroll
        for (int kk = 0; kk < 32; kk++) {
            const float* Ak = Ab + kk * 68 + warp * 8;
            const float* Bk = Bb + kk * 132 + tx * 4;
            ulonglong2 av0 = *(const ulonglong2*)(Ak);
            ulonglong2 av1 = *(const ulonglong2*)(Ak + 4);
            float4 bv = *(const float4*)(Bk);
            unsigned long long a2[4] = {av0.x, av0.y, av1.x, av1.y};
            unsigned long long b2[4];
            PACK2(b2[0], bv.x, bv.x);
            PACK2(b2[1], bv.y, bv.y);
            PACK2(b2[2], bv.z, bv.z);
            PACK2(b2[3], bv.w, bv.w);
            #pragma unroll
            for (int i = 0; i < 4; i++)
                #pragma unroll
                for (int j = 0; j < 4; j++)
                    FMA2(acc2[i][j], a2[i], b2[j], acc2[i][j]);
        }
        if (has_next) {
            const int nb = cur ^ 1;
            float* Ad = As + nb * 2176;
            #pragma unroll
            for (int p = 0; p < 2; p++) {
                const int m = a_mr + p * 32;
                Ad[(a_kp * 4 + 0) * 68 + m] = Ag[p].x;
                Ad[(a_kp * 4 + 1) * 68 + m] = Ag[p].y;
                Ad[(a_kp * 4 + 2) * 68 + m] = Ag[p].z;
                Ad[(a_kp * 4 + 3) * 68 + m] = Ag[p].w;
            }
            float* Bd = Bs + nb * 4224;
            #pragma unroll
            for (int p = 0; p < 4; p++)
                *(float4*)&Bd[(b_kr + p * 8) * 132 + b_n4 * 4] = Bg[p];
        }
        __syncthreads();
        cur ^= 1;
    }

    #pragma unroll
    for (int ip = 0; ip < 4; ip++) {
        const int r0 = m0 + warp * 8 + ip * 2;
        #pragma unroll
        for (int j = 0; j < 4; j++) {
            const int c = n0 + tx * 4 + j;
            if (c >= N) continue;
            float v0, v1;
            UNPK2(v0, v1, acc2[ip][j]);
            if (r0 < M)     C[(size_t)r0 * N + c]       = v0;
            if (r0 + 1 < M) C[(size_t)(r0 + 1) * N + c] = v1;
        }
    }
}

// ---------------- prep: split static weights to bf16 hi/lo ----------------
__global__ void prep_kernel(const float* __restrict__ W_ih, const float* __restrict__ W_hh,
                            const float* __restrict__ b_ih, const float* __restrict__ b_hh)
{
    const long total = (long)NG * KC2;
    for (long idx = (long)blockIdx.x * blockDim.x + threadIdx.x; idx < total;
         idx += (long)gridDim.x * blockDim.x) {
        int j = (int)(idx / KC2);
        int k = (int)(idx % KC2);
        float v = (k < ENCD) ? W_ih[(size_t)j * 2560 + 512 + k]
                             : W_hh[(size_t)j * 512 + (k - ENCD)];
        __nv_bfloat16 h = __float2bfloat16_rn(v);
        g_Wch_h[idx] = h;
        g_Wch_l[idx] = __float2bfloat16_rn(v - __bfloat162float(h));
    }
    const long te = (long)NG * EE;
    for (long idx = (long)blockIdx.x * blockDim.x + threadIdx.x; idx < te;
         idx += (long)gridDim.x * blockDim.x) {
        int j = (int)(idx / EE);
        int e = (int)(idx % EE);
        float v = W_ih[(size_t)j * 2560 + e];
        __nv_bfloat16 h = __float2bfloat16_rn(v);
        g_Wemb_h[idx] = h;
        g_Wemb_l[idx] = __float2bfloat16_rn(v - __bfloat162float(h));
    }
    int idx = blockIdx.x * blockDim.x + threadIdx.x;
    if (idx < NG) g_bcat[idx] = b_ih[idx] + b_hh[idx];
}

// transpose (Kd x Nd) -> (Nd x Kd) with bf16 hi/lo split
__global__ void transpose_split(const float* __restrict__ in,
                                __nv_bfloat16* __restrict__ oh,
                                __nv_bfloat16* __restrict__ ol, int Kd, int Nd)
{
    __shared__ float tile[32][33];
    const int kb = blockIdx.y * 32, nb = blockIdx.x * 32;
    const int tx = threadIdx.x, ty = threadIdx.y;  // 32 x 8
    #pragma unroll
    for (int p = 0; p < 4; p++) {
        const int k = kb + ty + p * 8, n = nb + tx;
        if (k < Kd && n < Nd) tile[ty + p * 8][tx] = in[(size_t)k * Nd + n];
    }
    __syncthreads();
    #pragma unroll
    for (int p = 0; p < 4; p++) {
        const int n = nb + ty + p * 8, k = kb + tx;
        if (n < Nd && k < Kd) {
            float v = tile[tx][ty + p * 8];
            __nv_bfloat16 h = __float2bfloat16_rn(v);
            oh[(size_t)n * Kd + k] = h;
            ol[(size_t)n * Kd + k] = __float2bfloat16_rn(v - __bfloat162float(h));
        }
    }
}

// ---------------- small kernels ----------------
__global__ void gather_emb(const int* __restrict__ captions,
                           const float* __restrict__ emb_table)
{
    int idx = blockIdx.x * blockDim.x + threadIdx.x;
    if (idx >= TT * BB * EE) return;
    int e  = idx & 511;
    int rb = idx >> 9;
    int tq = rb >> 6, bq = rb & 63;
    g_Eall[idx] = emb_table[(size_t)captions[bq * TT + tq] * EE + e];
}

__global__ void mean_kernel(const float* __restrict__ enc_out)
{
    const int b = blockIdx.x, tid = threadIdx.x;
    for (int e = tid; e < ENCD; e += 256) {
        const float* p = enc_out + (size_t)b * LL * ENCD + e;
        float s = 0.f;
        #pragma unroll 7
        for (int l = 0; l < LL; l++) s += p[(size_t)l * ENCD];
        g_mean[b * ENCD + e] = s * (1.f / (float)LL);
    }
}

__global__ void init_reduce(const float* __restrict__ b_init_h,
                            const float* __restrict__ b_init_c)
{
    int idx = blockIdx.x * blockDim.x + threadIdx.x;
    int b = idx >> 9, d = idx & 511;
    float h = b_init_h[d], c = b_init_c[d];
    #pragma unroll
    for (int z = 0; z < 8; z++) {
        h += g_ph[z * (BB * DD) + idx];
        c += g_pc[z * (BB * DD) + idx];
    }
    g_h[idx] = h;
    g_c[idx] = c;
    g_X2[(size_t)b * KC2 + ENCD + d] = h;
}

__device__ __forceinline__ float sigmoidf(float x) { return 1.f / (1.f + expf(-x)); }

__global__ void lstm_finalize(int t)
{
    int idx = blockIdx.x * blockDim.x + threadIdx.x;
    int b = idx >> 9, d = idx & 511;
    const float* ge = g_Gemb + ((size_t)t * BB + b) * NG;
    float gi = g_bcat[d]        + ge[d];
    float gf = g_bcat[512 + d]  + ge[512 + d];
    float gg = g_bcat[1024 + d] + ge[1024 + d];
    float go = g_bcat[1536 + d] + ge[1536 + d];
    #pragma unroll
    for (int z = 0; z < 10; z++) {
        const float* p = g_gpart + ((size_t)z * BB + b) * NG;
        gi += p[d]; gf += p[512 + d]; gg += p[1024 + d]; go += p[1536 + d];
    }
    float i = sigmoidf(gi), f = sigmoidf(gf), o = sigmoidf(go), g = tanhf(gg);
    float c = f * g_c[idx] + i * g;
    float h = o * tanhf(c);
    g_c[idx] = c;
    g_h[idx] = h;
    g_X2[(size_t)b * KC2 + ENCD + d] = h;
    g_hall[((size_t)t * BB + b) * DD + d] = h;
}

__global__ void att_kernel(const float* __restrict__ enc_out,
                           const float* __restrict__ b_dec_att,
                           const float* __restrict__ w_full,
                           const float* __restrict__ b_full,
                           float* __restrict__ alphas_out, int t)
{
    __shared__ float sh_dec[AA];
    __shared__ float sh_w[AA];
    __shared__ float sh_sc[64];

    const int b = blockIdx.x, tid = threadIdx.x;
    for (int a = tid; a < AA; a += 256) {
        float s = b_dec_att[a];
        #pragma unroll
        for (int z = 0; z < 8; z++) s += g_decp[((size_t)z * BB + b) * AA + a];
        sh_dec[a] = s;
        sh_w[a]   = w_full[a];
    }
    __syncthreads();

    const int warp = tid >> 5, lane = tid & 31;
    for (int l = warp; l < LL; l += 8) {
        const float* ep = g_encproj + ((size_t)b * LL + l) * AA;
        float s = 0.f;
        for (int a = lane; a < AA; a += 32) {
            float v = ep[a] + sh_dec[a];
            v = fmaxf(v, 0.f);
            s = fmaf(v, sh_w[a], s);
        }
        #pragma unroll
        for (int o = 16; o; o >>= 1) s += __shfl_xor_sync(0xffffffffu, s, o);
        if (lane == 0) sh_sc[l] = s + b_full[0];
    }
    __syncthreads();

    if (warp == 0) {
        float v0 = (lane < LL) ? sh_sc[lane] : -1e30f;
        float v1 = (lane + 32 < LL) ? sh_sc[lane + 32] : -1e30f;
        float mx = fmaxf(v0, v1);
        #pragma unroll
        for (int o = 16; o; o >>= 1) mx = fmaxf(mx, __shfl_xor_sync(0xffffffffu, mx, o));
        float e0 = (lane < LL) ? expf(v0 - mx) : 0.f;
        float e1 = (lane + 32 < LL) ? expf(v1 - mx) : 0.f;
        float ssum = e0 + e1;
        #pragma unroll
        for (int o = 16; o; o >>= 1) ssum += __shfl_xor_sync(0xffffffffu, ssum, o);
        float inv = 1.f / ssum;
        if (lane < LL) sh_sc[lane] = e0 * inv;
        if (lane + 32 < LL) sh_sc[lane + 32] = e1 * inv;
    }
    __syncthreads();

    for (int l = tid; l < LL; l += 256)
        alphas_out[((size_t)b * TT + t) * LL + l] = sh_sc[l];

    for (int e = tid; e < ENCD; e += 256) {
        const float* eb = enc_out + (size_t)b * LL * ENCD + e;
        float s = 0.f;
        #pragma unroll 7
        for (int l = 0; l < LL; l++) s = fmaf(sh_sc[l], eb[(size_t)l * ENCD], s);
        g_X2[(size_t)b * KC2 + e] = s;
    }
}

__global__ void ep_bias(const float* __restrict__ b_enc_att)
{
    int idx = blockIdx.x * blockDim.x + threadIdx.x;  // BB*LL*AA
    g_encproj[idx] += b_enc_att[idx & 511];
}

// ---------------- host launch ----------------
extern "C" void kernel_launch(void* const* d_in, const int* in_sizes, int n_in,
                              void* d_out, int out_size)
{
    const float* enc_out    = (const float*)d_in[0];
    const int*   captions   = (const int*)  d_in[1];
    const float* emb_table  = (const float*)d_in[2];
    const float* W_enc_att  = (const float*)d_in[3];
    const float* b_enc_att  = (const float*)d_in[4];
    const float* W_dec_att  = (const float*)d_in[5];
    const float* b_dec_att  = (const float*)d_in[6];
    const float* w_full     = (const float*)d_in[7];
    const float* b_full     = (const float*)d_in[8];
    const float* W_ih       = (const float*)d_in[9];
    const float* b_ih       = (const float*)d_in[10];
    const float* W_hh       = (const float*)d_in[11];
    const float* b_hh       = (const float*)d_in[12];
    const float* W_init_h   = (const float*)d_in[13];
    const float* b_init_h   = (const float*)d_in[14];
    const float* W_init_c   = (const float*)d_in[15];
    const float* b_init_c   = (const float*)d_in[16];
    const float* W_out      = (const float*)d_in[17];
    const float* b_out      = (const float*)d_in[18];
    float* out = (float*)d_out;
    float* alphas = out + (size_t)BB * TT * VV;

    cudaFuncSetAttribute(gemm_f32, cudaFuncAttributeMaxDynamicSharedMemorySize, SMEMB);
    cudaFuncSetAttribute(mma_gemm<128, 0>, cudaFuncAttributeMaxDynamicSharedMemorySize, 65536);
    cudaFuncSetAttribute(mma_gemm<128, 1>, cudaFuncAttributeMaxDynamicSharedMemorySize, 65536);
    cudaFuncSetAttribute(mma_gemm<64, 0>,  cudaFuncAttributeMaxDynamicSharedMemorySize, 49152);

    float *p_mean, *p_Eall, *p_Gemb, *p_h, *p_X2, *p_hall,
          *p_ph, *p_pc, *p_decp, *p_gpart, *p_encproj;
    __nv_bfloat16 *pWch_h, *pWch_l, *pWout_h, *pWout_l, *pWenc_h, *pWenc_l, *pWemb_h, *pWemb_l;
    cudaGetSymbolAddress((void**)&p_mean,    g_mean);
    cudaGetSymbolAddress((void**)&p_Eall,    g_Eall);
    cudaGetSymbolAddress((void**)&p_Gemb,    g_Gemb);
    cudaGetSymbolAddress((void**)&p_h,       g_h);
    cudaGetSymbolAddress((void**)&p_X2,      g_X2);
    cudaGetSymbolAddress((void**)&p_hall,    g_hall);
    cudaGetSymbolAddress((void**)&p_ph,      g_ph);
    cudaGetSymbolAddress((void**)&p_pc,      g_pc);
    cudaGetSymbolAddress((void**)&p_decp,    g_decp);
    cudaGetSymbolAddress((void**)&p_gpart,   g_gpart);
    cudaGetSymbolAddress((void**)&p_encproj, g_encproj);
    cudaGetSymbolAddress((void**)&pWch_h,    g_Wch_h);
    cudaGetSymbolAddress((void**)&pWch_l,    g_Wch_l);
    cudaGetSymbolAddress((void**)&pWout_h,   g_Wout_h);
    cudaGetSymbolAddress((void**)&pWout_l,   g_Wout_l);
    cudaGetSymbolAddress((void**)&pWenc_h,   g_Wenc_h);
    cudaGetSymbolAddress((void**)&pWenc_l,   g_Wenc_l);
    cudaGetSymbolAddress((void**)&pWemb_h,   g_Wemb_h);
    cudaGetSymbolAddress((void**)&pWemb_l,   g_Wemb_l);

    // ---- one-time setup
    prep_kernel<<<4096, 256>>>(W_ih, W_hh, b_ih, b_hh);
    gather_emb<<<2560, 256>>>(captions, emb_table);
    mean_kernel<<<BB, 256>>>(enc_out);
    transpose_split<<<dim3((VV + 31) / 32, (DD + 31) / 32), dim3(32, 8)>>>(W_out, pWout_h, pWout_l, DD, VV);
    transpose_split<<<dim3((AA + 31) / 32, (ENCD + 31) / 32), dim3(32, 8)>>>(W_enc_att, pWenc_h, pWenc_l, ENCD, AA);

    // Gemb (1280 x 2048) = Eall(1280x512) @ Wemb(2048x512)^T
    mma_gemm<128, 0><<<dim3(16, 10), 256, 65536>>>(p_Eall, EE, pWemb_h, pWemb_l, EE, nullptr,
                                                   p_Gemb, NG, TT * BB, NG, EE);
    // h0/c0 (tiny, fp32 path, split-K 8)
    gemm_f32<<<dim3(4, 1, 8), 256, SMEMB>>>(p_mean, ENCD, W_init_h, DD, p_ph, BB, DD, 256);
    gemm_f32<<<dim3(4, 1, 8), 256, SMEMB>>>(p_mean, ENCD, W_init_c, DD, p_pc, BB, DD, 256);
    init_reduce<<<128, 256>>>(b_init_h, b_init_c);
    // enc_proj (3136 x 512) = enc_out(3136x2048) @ Wenc(512x2048)^T + bias
    mma_gemm<128, 0><<<dim3(4, 25), 256, 65536>>>(enc_out, ENCD, pWenc_h, pWenc_l, ENCD, b_enc_att,
                                                  p_encproj, AA, BB * LL, AA, ENCD);

    // ---- sequential loop
    for (int t = 0; t < TT; t++) {
        // dec_proj partials (64x512) = h @ W_dec_att, split-K 8
        gemm_f32<<<dim3(4, 1, 8), 256, SMEMB>>>(p_h, DD, W_dec_att, AA, p_decp, BB, AA, 64);
        att_kernel<<<BB, 256>>>(enc_out, b_dec_att, w_full, b_full, alphas, t);
        // gates partials (64x2048) = X2(64x2560) @ Wch^T, tensor path, split-K 10 (Kc=256)
        mma_gemm<64, 0><<<dim3(16, 1, 10), 256, 49152>>>(p_X2, KC2, pWch_h, pWch_l, KC2, nullptr,
                                                         p_gpart, NG, BB, NG, 256);
        lstm_finalize<<<128, 256>>>(t);
    }

    // ---- batched logits (1280 x 10000) = hall @ Wout^T, (b,t) scatter + bias
    mma_gemm<128, 1><<<dim3(79, 10), 256, 65536>>>(p_hall, DD, pWout_h, pWout_l, DD, b_out,
                                                   out, VV, TT * BB, VV, DD);
}